// round 4
// baseline (speedup 1.0000x reference)
#include <cuda_runtime.h>
#include <math.h>

#define NTHREADS 128
#define HID 64
#define GRID 296   // 2 CTAs/SM * 148 SMs

typedef unsigned long long u64;

// ---------------- SMEM layout (float offsets) ----------------
#define OFF_SW1 0
#define OFF_SB1 448
#define OFF_SW2 512
#define OFF_SB2 4608
#define OFF_SW3 4672
#define OFF_SB3 4736
#define OFF_AW1 4740
#define OFF_AB1 5188
#define OFF_AW2 5252
#define OFF_AB2 9348
#define OFF_AW3 9412
#define OFF_AB3 9476
#define OFF_FW1 9480
#define OFF_FB1 9864
#define OFF_FW2 9928
#define OFF_FB2 14024
#define OFF_FW3 14088
#define OFF_FB3 14152
#define OFF_RW1 14156
#define OFF_RB1 14476
#define OFF_RW2 14540
#define OFF_RB2 18636
#define OFF_RW3 18700
#define OFF_RB3 18892
#define OFF_IMEAN 18896
#define OFF_ISTD  18904
#define OFF_TMEAN 18912
#define OFF_TSTD  18916
#define SMEM_FLOATS 18920
#define SMEM_BYTES (SMEM_FLOATS * 4)

struct KParams {
    const float* in[30];
    float* out;
    int B;
};

__device__ __constant__ int kCnt[28] = {
    5, 5, 3, 3,
    448, 64, 4096, 64, 64, 1,
    448, 64, 4096, 64, 64, 1,
    384, 64, 4096, 64, 64, 1,
    320, 64, 4096, 64, 192, 3
};
__device__ __constant__ int kOff[28] = {
    OFF_IMEAN, OFF_ISTD, OFF_TMEAN, OFF_TSTD,
    OFF_SW1, OFF_SB1, OFF_SW2, OFF_SB2, OFF_SW3, OFF_SB3,
    OFF_AW1, OFF_AB1, OFF_AW2, OFF_AB2, OFF_AW3, OFF_AB3,
    OFF_FW1, OFF_FB1, OFF_FW2, OFF_FB2, OFF_FW3, OFF_FB3,
    OFF_RW1, OFF_RB1, OFF_RW2, OFF_RB2, OFF_RW3, OFF_RB3
};

// ---------------- packed f32x2 helpers ----------------
__device__ __forceinline__ u64 dup2(float a) {
    u64 r; asm("mov.b64 %0, {%1, %1};" : "=l"(r) : "f"(a)); return r;
}
__device__ __forceinline__ u64 ffma2(u64 a, u64 b, u64 c) {
    u64 d; asm("fma.rn.f32x2 %0, %1, %2, %3;" : "=l"(d) : "l"(a), "l"(b), "l"(c)); return d;
}
__device__ __forceinline__ float2 unpk2(u64 a) {
    float2 f; asm("mov.b64 {%0, %1}, %2;" : "=f"(f.x), "=f"(f.y) : "l"(a)); return f;
}

// accurate fast tanh: abs error ~1e-7, 2 MUFU (EX2 + RCP)
__device__ __forceinline__ float fast_tanhf(float x) {
    float ax = fabsf(x);
    float e  = __expf(2.0f * ax);
    float t  = 1.0f - __fdividef(2.0f, e + 1.0f);
    return (x < 0.0f) ? -t : t;
}

__device__ __forceinline__ float softplusf(float x) {
    float t = __expf(-fabsf(x));
    return fmaxf(x, 0.0f) + __logf(1.0f + t);
}

// Two rows through one MLP: DIN -> 64 (tanh) -> 64 (tanh) -> DOUT.
// Layer-1 computed in two 32-wide halves; each half's activations are
// consumed immediately by a partial layer-2 accumulation so only 32
// h-values per row are live at once. Every weight LDS feeds 4 FFMA2.
template <int DIN, int DOUT>
__device__ __forceinline__ void run_mlp2(
    const float* __restrict__ xa, const float* __restrict__ xb,
    const float* __restrict__ sm,
    int oW1, int ob1, int oW2, int ob2, int oW3, int ob3,
    float* __restrict__ outa, float* __restrict__ outb)
{
    u64 acc2a[32], acc2b[32];
    {
        const u64* b2 = (const u64*)(sm + ob2);
#pragma unroll
        for (int j = 0; j < 32; j++) { u64 b = b2[j]; acc2a[j] = b; acc2b[j] = b; }
    }

#pragma unroll
    for (int half = 0; half < 2; half++) {
        // ---- layer 1, output cols [half*32, half*32+32) ----
        u64 acc1a[16], acc1b[16];
        {
            const u64* b1 = (const u64*)(sm + ob1 + half * 32);
#pragma unroll
            for (int j = 0; j < 16; j++) { u64 b = b1[j]; acc1a[j] = b; acc1b[j] = b; }
        }
#pragma unroll
        for (int i = 0; i < DIN; i++) {
            const u64* w = (const u64*)(sm + oW1 + i * HID + half * 32);
            u64 x2a = dup2(xa[i]);
            u64 x2b = dup2(xb[i]);
#pragma unroll
            for (int j = 0; j < 16; j++) {
                u64 wj = w[j];
                acc1a[j] = ffma2(x2a, wj, acc1a[j]);
                acc1b[j] = ffma2(x2b, wj, acc1b[j]);
            }
        }
        float ha[32], hb[32];
#pragma unroll
        for (int j = 0; j < 16; j++) {
            float2 va = unpk2(acc1a[j]);
            ha[2*j]   = fast_tanhf(va.x);
            ha[2*j+1] = fast_tanhf(va.y);
            float2 vb = unpk2(acc1b[j]);
            hb[2*j]   = fast_tanhf(vb.x);
            hb[2*j+1] = fast_tanhf(vb.y);
        }
        // ---- layer 2 partial: reduction rows i = half*32 + k ----
#pragma unroll
        for (int k = 0; k < 32; k++) {
            const u64* w = (const u64*)(sm + oW2 + (half * 32 + k) * HID);
            u64 h2a = dup2(ha[k]);
            u64 h2b = dup2(hb[k]);
#pragma unroll
            for (int j = 0; j < 32; j++) {
                u64 wj = w[j];
                acc2a[j] = ffma2(h2a, wj, acc2a[j]);
                acc2b[j] = ffma2(h2b, wj, acc2b[j]);
            }
        }
    }

    // ---- layer 3: tanh(acc2) -> DOUT, streaming ----
    float oa[DOUT], ob_[DOUT];
#pragma unroll
    for (int o = 0; o < DOUT; o++) { float b = sm[ob3 + o]; oa[o] = b; ob_[o] = b; }
#pragma unroll
    for (int j = 0; j < 32; j++) {
        float2 va = unpk2(acc2a[j]);
        float ta0 = fast_tanhf(va.x), ta1 = fast_tanhf(va.y);
        float2 vb = unpk2(acc2b[j]);
        float tb0 = fast_tanhf(vb.x), tb1 = fast_tanhf(vb.y);
#pragma unroll
        for (int o = 0; o < DOUT; o++) {
            float w0 = sm[oW3 + (2*j)   * DOUT + o];
            float w1 = sm[oW3 + (2*j+1) * DOUT + o];
            oa[o]  = fmaf(ta0, w0, fmaf(ta1, w1, oa[o]));
            ob_[o] = fmaf(tb0, w0, fmaf(tb1, w1, ob_[o]));
        }
    }
#pragma unroll
    for (int o = 0; o < DOUT; o++) { outa[o] = oa[o]; outb[o] = ob_[o]; }
}

extern __shared__ float sm[];

__global__ void __launch_bounds__(NTHREADS, 2)
fused_mlp_kernel(KParams p)
{
    const int tid = threadIdx.x;

    // Stage all weights + norm params into SMEM once per CTA.
    for (int a = 0; a < 28; a++) {
        const float* src = p.in[a + 2];
        const int n = kCnt[a];
        const int o = kOff[a];
        for (int k = tid; k < n; k += NTHREADS) sm[o + k] = src[k];
    }
    __syncthreads();

    const float* xd0 = p.in[0];
    const float* utr = p.in[1];
    const int Btot = p.B;
    const int npairs = (Btot + 1) >> 1;
    const int stride = gridDim.x * NTHREADS;

    const float im0 = sm[OFF_IMEAN+0], im1 = sm[OFF_IMEAN+1], im2 = sm[OFF_IMEAN+2];
    const float im3 = sm[OFF_IMEAN+3], im4 = sm[OFF_IMEAN+4];
    const float is0 = sm[OFF_ISTD+0],  is1 = sm[OFF_ISTD+1],  is2 = sm[OFF_ISTD+2];
    const float is3 = sm[OFF_ISTD+3],  is4 = sm[OFF_ISTD+4];

    for (int pr = blockIdx.x * NTHREADS + tid; pr < npairs; pr += stride) {
        int ra = 2 * pr;
        int rb = 2 * pr + 1;
        bool hasb = (rb < Btot);
        int rbe = hasb ? rb : ra;

        float fa[5], fb[5]; // vx, vy, w, vel, delta per row
        {
            float a0 = xd0[ra*3+0], a1 = xd0[ra*3+1], a2 = xd0[ra*3+2];
            float a3 = utr[ra*2+0], a4 = utr[ra*2+1];
            fa[0] = __fdividef(a0 - im0, is0);
            fa[1] = __fdividef(a1 - im1, is1);
            fa[2] = __fdividef(a2 - im2, is2);
            fa[3] = __fdividef(a3 - im3, is3);
            fa[4] = __fdividef(a4 - im4, is4);
            float b0 = xd0[rbe*3+0], b1 = xd0[rbe*3+1], b2 = xd0[rbe*3+2];
            float b3 = utr[rbe*2+0], b4 = utr[rbe*2+1];
            fb[0] = __fdividef(b0 - im0, is0);
            fb[1] = __fdividef(b1 - im1, is1);
            fb[2] = __fdividef(b2 - im2, is2);
            fb[3] = __fdividef(b3 - im3, is3);
            fb[4] = __fdividef(b4 - im4, is4);
        }
        float vma = sqrtf(fmaf(fa[0], fa[0], fmaf(fa[1], fa[1], 1e-8f)));
        float vmb = sqrtf(fmaf(fb[0], fb[0], fmaf(fb[1], fb[1], 1e-8f)));
        float sga = (fa[0] > 0.0f) ? 1.0f : ((fa[0] < 0.0f) ? -1.0f : 0.0f);
        float sgb = (fb[0] > 0.0f) ? 1.0f : ((fb[0] < 0.0f) ? -1.0f : 0.0f);

        // steer MLP: [delta, vel, vx, vy, w, mag, sign]
        float sia[7] = {fa[4], fa[3], fa[0], fa[1], fa[2], vma, sga};
        float sib[7] = {fb[4], fb[3], fb[0], fb[1], fb[2], vmb, sgb};
        float soa, sob;
        run_mlp2<7,1>(sia, sib, sm, OFF_SW1, OFF_SB1, OFF_SW2, OFF_SB2, OFF_SW3, OFF_SB3, &soa, &sob);
        float dsa = 0.5f * fast_tanhf(soa);
        float dsb = 0.5f * fast_tanhf(sob);

        // acc MLP: [vel, delta, vx, mag, sign, vy, w]
        float aia[7] = {fa[3], fa[4], fa[0], vma, sga, fa[1], fa[2]};
        float aib[7] = {fb[3], fb[4], fb[0], vmb, sgb, fb[1], fb[2]};
        float aoa, aob;
        run_mlp2<7,1>(aia, aib, sm, OFF_AW1, OFF_AB1, OFF_AW2, OFF_AB2, OFF_AW3, OFF_AB3, &aoa, &aob);
        float daa = 0.5f * fast_tanhf(aoa);
        float dab = 0.5f * fast_tanhf(aob);

        float ue0a = fa[3] + daa, ue1a = fa[4] + dsa;
        float ue0b = fb[3] + dab, ue1b = fb[4] + dsb;

        // friction MLP: [vx, vy, w, ue0, ue1, DT]
        float fia[6] = {fa[0], fa[1], fa[2], ue0a, ue1a, 0.02f};
        float fib[6] = {fb[0], fb[1], fb[2], ue0b, ue1b, 0.02f};
        float foa, fob;
        run_mlp2<6,1>(fia, fib, sm, OFF_FW1, OFF_FB1, OFF_FW2, OFF_FB2, OFF_FW3, OFF_FB3, &foa, &fob);
        float fka = 1.0f + softplusf(foa);
        float fkb = 1.0f + softplusf(fob);

        // residual MLP: [vx, vy, w, ue0, ue1]
        float ria[5] = {fa[0], fa[1], fa[2], ue0a, ue1a};
        float rib[5] = {fb[0], fb[1], fb[2], ue0b, ue1b};
        float roa[3], rob[3];
        run_mlp2<5,3>(ria, rib, sm, OFF_RW1, OFF_RB1, OFF_RW2, OFF_RB2, OFF_RW3, OFF_RB3, roa, rob);

        float ts0 = sm[OFF_TSTD+0], ts1 = sm[OFF_TSTD+1], ts2 = sm[OFF_TSTD+2];
        float tm0 = sm[OFF_TMEAN+0], tm1 = sm[OFF_TMEAN+1], tm2 = sm[OFF_TMEAN+2];

        // outputs: [ut_eff_raw (B,2)] [friction_k (B,1)] [residual (B,3)]
        p.out[ra*2+0] = fmaf(ue0a, is3, im3);
        p.out[ra*2+1] = fmaf(ue1a, is4, im4);
        p.out[2*Btot + ra] = fka;
        p.out[3*Btot + ra*3 + 0] = fmaf(roa[0], ts0, tm0);
        p.out[3*Btot + ra*3 + 1] = fmaf(roa[1], ts1, tm1);
        p.out[3*Btot + ra*3 + 2] = fmaf(roa[2], ts2, tm2);
        if (hasb) {
            p.out[rb*2+0] = fmaf(ue0b, is3, im3);
            p.out[rb*2+1] = fmaf(ue1b, is4, im4);
            p.out[2*Btot + rb] = fkb;
            p.out[3*Btot + rb*3 + 0] = fmaf(rob[0], ts0, tm0);
            p.out[3*Btot + rb*3 + 1] = fmaf(rob[1], ts1, tm1);
            p.out[3*Btot + rb*3 + 2] = fmaf(rob[2], ts2, tm2);
        }
    }
}

extern "C" void kernel_launch(void* const* d_in, const int* in_sizes, int n_in,
                              void* d_out, int out_size)
{
    KParams p;
    for (int i = 0; i < 30; i++) p.in[i] = (const float*)d_in[i];
    p.out = (float*)d_out;
    p.B = in_sizes[0] / 3;

    cudaFuncSetAttribute(fused_mlp_kernel,
                         cudaFuncAttributeMaxDynamicSharedMemorySize, SMEM_BYTES);
    fused_mlp_kernel<<<GRID, NTHREADS, SMEM_BYTES>>>(p);
}

// round 5
// speedup vs baseline: 1.2604x; 1.2604x over previous
#include <cuda_runtime.h>
#include <math.h>

#define NTHREADS 128
#define HID 64
#define GRID 444   // 3 CTAs/SM * 148 SMs

typedef unsigned long long u64;

// ---------------- SMEM layout (float offsets) ----------------
#define OFF_SW1 0
#define OFF_SB1 448
#define OFF_SW2 512
#define OFF_SB2 4608
#define OFF_SW3 4672
#define OFF_SB3 4736
#define OFF_AW1 4740
#define OFF_AB1 5188
#define OFF_AW2 5252
#define OFF_AB2 9348
#define OFF_AW3 9412
#define OFF_AB3 9476
#define OFF_FW1 9480
#define OFF_FB1 9864
#define OFF_FW2 9928
#define OFF_FB2 14024
#define OFF_FW3 14088
#define OFF_FB3 14152
#define OFF_RW1 14156
#define OFF_RB1 14476
#define OFF_RW2 14540
#define OFF_RB2 18636
#define OFF_RW3 18700
#define OFF_RB3 18892
#define OFF_IMEAN 18896
#define OFF_ISTD  18904
#define OFF_TMEAN 18912
#define OFF_TSTD  18916
#define SMEM_FLOATS 18920
#define SMEM_BYTES (SMEM_FLOATS * 4)

struct KParams {
    const float* in[30];
    float* out;
    int B;
};

__device__ __constant__ int kCnt[28] = {
    5, 5, 3, 3,
    448, 64, 4096, 64, 64, 1,
    448, 64, 4096, 64, 64, 1,
    384, 64, 4096, 64, 64, 1,
    320, 64, 4096, 64, 192, 3
};
__device__ __constant__ int kOff[28] = {
    OFF_IMEAN, OFF_ISTD, OFF_TMEAN, OFF_TSTD,
    OFF_SW1, OFF_SB1, OFF_SW2, OFF_SB2, OFF_SW3, OFF_SB3,
    OFF_AW1, OFF_AB1, OFF_AW2, OFF_AB2, OFF_AW3, OFF_AB3,
    OFF_FW1, OFF_FB1, OFF_FW2, OFF_FB2, OFF_FW3, OFF_FB3,
    OFF_RW1, OFF_RB1, OFF_RW2, OFF_RB2, OFF_RW3, OFF_RB3
};

// ---------------- packed f32x2 helpers ----------------
__device__ __forceinline__ u64 dup2(float a) {
    u64 r; asm("mov.b64 %0, {%1, %1};" : "=l"(r) : "f"(a)); return r;
}
__device__ __forceinline__ u64 ffma2(u64 a, u64 b, u64 c) {
    u64 d; asm("fma.rn.f32x2 %0, %1, %2, %3;" : "=l"(d) : "l"(a), "l"(b), "l"(c)); return d;
}
__device__ __forceinline__ float2 unpk2(u64 a) {
    float2 f; asm("mov.b64 {%0, %1}, %2;" : "=f"(f.x), "=f"(f.y) : "l"(a)); return f;
}

// accurate fast tanh: abs error ~1e-7, 2 MUFU (EX2 + RCP)
__device__ __forceinline__ float fast_tanhf(float x) {
    float ax = fabsf(x);
    float e  = __expf(2.0f * ax);
    float t  = 1.0f - __fdividef(2.0f, e + 1.0f);
    return (x < 0.0f) ? -t : t;
}

__device__ __forceinline__ float softplusf(float x) {
    float t = __expf(-fabsf(x));
    return fmaxf(x, 0.0f) + __logf(1.0f + t);
}

// One full MLP: DIN -> 64 (tanh) -> 64 (tanh) -> DOUT.
// Hidden state in registers; weights via 128-bit smem broadcast loads
// (ld.shared.v2.u64), each feeding two packed FFMA2.
template <int DIN, int DOUT>
__device__ __forceinline__ void run_mlp(
    const float* __restrict__ x,
    const float* __restrict__ sm,
    int oW1, int ob1, int oW2, int ob2, int oW3, int ob3,
    float* __restrict__ outv)
{
    u64 acc[32];
    float h[HID];

    // ---- layer 1: DIN -> 64 ----
    {
        const ulonglong2* b2 = (const ulonglong2*)(sm + ob1);
#pragma unroll
        for (int j = 0; j < 16; j++) {
            ulonglong2 b = b2[j];
            acc[2*j] = b.x; acc[2*j+1] = b.y;
        }
    }
#pragma unroll
    for (int i = 0; i < DIN; i++) {
        u64 xi = dup2(x[i]);
        const ulonglong2* w = (const ulonglong2*)(sm + oW1 + i * HID);
#pragma unroll
        for (int j = 0; j < 16; j++) {
            ulonglong2 wv = w[j];
            acc[2*j]   = ffma2(xi, wv.x, acc[2*j]);
            acc[2*j+1] = ffma2(xi, wv.y, acc[2*j+1]);
        }
    }
#pragma unroll
    for (int j = 0; j < 32; j++) {
        float2 v = unpk2(acc[j]);
        h[2*j]   = fast_tanhf(v.x);
        h[2*j+1] = fast_tanhf(v.y);
    }

    // ---- layer 2: 64 -> 64 ----
    {
        const ulonglong2* b2 = (const ulonglong2*)(sm + ob2);
#pragma unroll
        for (int j = 0; j < 16; j++) {
            ulonglong2 b = b2[j];
            acc[2*j] = b.x; acc[2*j+1] = b.y;
        }
    }
#pragma unroll
    for (int i = 0; i < HID; i++) {
        u64 hi = dup2(h[i]);
        const ulonglong2* w = (const ulonglong2*)(sm + oW2 + i * HID);
#pragma unroll
        for (int j = 0; j < 16; j++) {
            ulonglong2 wv = w[j];
            acc[2*j]   = ffma2(hi, wv.x, acc[2*j]);
            acc[2*j+1] = ffma2(hi, wv.y, acc[2*j+1]);
        }
    }
#pragma unroll
    for (int j = 0; j < 32; j++) {
        float2 v = unpk2(acc[j]);
        h[2*j]   = fast_tanhf(v.x);
        h[2*j+1] = fast_tanhf(v.y);
    }

    // ---- layer 3: 64 -> DOUT ----
#pragma unroll
    for (int o = 0; o < DOUT; o++) outv[o] = sm[ob3 + o];
#pragma unroll
    for (int j = 0; j < HID; j++) {
        float hj = h[j];
#pragma unroll
        for (int o = 0; o < DOUT; o++)
            outv[o] = fmaf(hj, sm[oW3 + j * DOUT + o], outv[o]);
    }
}

extern __shared__ float sm[];

__global__ void __launch_bounds__(NTHREADS, 3)
fused_mlp_kernel(KParams p)
{
    const int tid = threadIdx.x;

    // Stage all weights + norm params into SMEM once per CTA.
    for (int a = 0; a < 28; a++) {
        const float* src = p.in[a + 2];
        const int n = kCnt[a];
        const int o = kOff[a];
        for (int k = tid; k < n; k += NTHREADS) sm[o + k] = src[k];
    }
    __syncthreads();

    const float* xd0 = p.in[0];
    const float* utr = p.in[1];
    const int Btot = p.B;
    const int stride = gridDim.x * NTHREADS;

    for (int row = blockIdx.x * NTHREADS + tid; row < Btot; row += stride) {
        float x0 = xd0[row * 3 + 0];
        float x1 = xd0[row * 3 + 1];
        float x2 = xd0[row * 3 + 2];
        float x3 = utr[row * 2 + 0];
        float x4 = utr[row * 2 + 1];

        float vx    = __fdividef(x0 - sm[OFF_IMEAN + 0], sm[OFF_ISTD + 0]);
        float vy    = __fdividef(x1 - sm[OFF_IMEAN + 1], sm[OFF_ISTD + 1]);
        float wz    = __fdividef(x2 - sm[OFF_IMEAN + 2], sm[OFF_ISTD + 2]);
        float vel   = __fdividef(x3 - sm[OFF_IMEAN + 3], sm[OFF_ISTD + 3]);
        float delta = __fdividef(x4 - sm[OFF_IMEAN + 4], sm[OFF_ISTD + 4]);

        float vmag  = sqrtf(fmaf(vx, vx, fmaf(vy, vy, 1e-8f)));
        float vsign = (vx > 0.0f) ? 1.0f : ((vx < 0.0f) ? -1.0f : 0.0f);

        // steer MLP
        float si[7] = {delta, vel, vx, vy, wz, vmag, vsign};
        float so;
        run_mlp<7, 1>(si, sm, OFF_SW1, OFF_SB1, OFF_SW2, OFF_SB2, OFF_SW3, OFF_SB3, &so);
        float d_steer = 0.5f * fast_tanhf(so);

        // acc MLP
        float ai[7] = {vel, delta, vx, vmag, vsign, vy, wz};
        float ao;
        run_mlp<7, 1>(ai, sm, OFF_AW1, OFF_AB1, OFF_AW2, OFF_AB2, OFF_AW3, OFF_AB3, &ao);
        float d_acc = 0.5f * fast_tanhf(ao);

        float ue0 = vel + d_acc;
        float ue1 = delta + d_steer;

        // friction MLP
        float fi[6] = {vx, vy, wz, ue0, ue1, 0.02f};
        float fo;
        run_mlp<6, 1>(fi, sm, OFF_FW1, OFF_FB1, OFF_FW2, OFF_FB2, OFF_FW3, OFF_FB3, &fo);
        float friction_k = 1.0f + softplusf(fo);

        // residual MLP
        float ri[5] = {vx, vy, wz, ue0, ue1};
        float ro[3];
        run_mlp<5, 3>(ri, sm, OFF_RW1, OFF_RB1, OFF_RW2, OFF_RB2, OFF_RW3, OFF_RB3, ro);

        float r0 = fmaf(ro[0], sm[OFF_TSTD + 0], sm[OFF_TMEAN + 0]);
        float r1 = fmaf(ro[1], sm[OFF_TSTD + 1], sm[OFF_TMEAN + 1]);
        float r2 = fmaf(ro[2], sm[OFF_TSTD + 2], sm[OFF_TMEAN + 2]);

        float u0 = fmaf(ue0, sm[OFF_ISTD + 3], sm[OFF_IMEAN + 3]);
        float u1 = fmaf(ue1, sm[OFF_ISTD + 4], sm[OFF_IMEAN + 4]);

        // outputs: [ut_eff_raw (B,2)] [friction_k (B,1)] [residual (B,3)]
        p.out[row * 2 + 0] = u0;
        p.out[row * 2 + 1] = u1;
        p.out[2 * Btot + row] = friction_k;
        p.out[3 * Btot + row * 3 + 0] = r0;
        p.out[3 * Btot + row * 3 + 1] = r1;
        p.out[3 * Btot + row * 3 + 2] = r2;
    }
}

extern "C" void kernel_launch(void* const* d_in, const int* in_sizes, int n_in,
                              void* d_out, int out_size)
{
    KParams p;
    for (int i = 0; i < 30; i++) p.in[i] = (const float*)d_in[i];
    p.out = (float*)d_out;
    p.B = in_sizes[0] / 3;

    cudaFuncSetAttribute(fused_mlp_kernel,
                         cudaFuncAttributeMaxDynamicSharedMemorySize, SMEM_BYTES);
    fused_mlp_kernel<<<GRID, NTHREADS, SMEM_BYTES>>>(p);
}